// round 13
// baseline (speedup 1.0000x reference)
#include <cuda_runtime.h>
#include <math.h>

#define N_NODES 100000
#define N_EDGES 3200000
#define GRID    296
#define BLOCK   256
#define GSTRIDE (GRID * BLOCK)
#define CHUNK   512
#define NCHUNK  ((N_NODES + CHUNK - 1) / CHUNK)   // 196
#define NTILE16 (N_NODES / 16)                    // 6250
#define NTILE64 ((N_NODES + 63) / 64)             // 1563

// ---------------- scratch (device globals) -----------------------------------
__device__ int    g_src[N_EDGES];
__device__ int    g_dst[N_EDGES];
__device__ int2   g_pk[N_EDGES];                 // dst-bucketed {src, norm}
__device__ unsigned long long g_dc[N_NODES];     // packed: cnt<<40 | deg*2^24
__device__ int    g_off[N_NODES + 1];
__device__ int    g_cur[N_NODES];
__device__ int    g_bsum[NCHUNK];
__device__ float  g_dinv[N_NODES];
__device__ float  g_h1[N_NODES * 16];
__device__ float  g_h2[N_NODES * 16];
__device__ float  g_c[N_NODES];
__device__ float  g_hsum[16];
__device__ float  g_pmax[GRID];
__device__ float  g_psum[GRID];
__device__ int    g_is64;
__device__ unsigned int          g_barcnt = 0;
__device__ volatile unsigned int g_bargen = 0;

// ---------------- helpers -----------------------------------------------------
__device__ __forceinline__ float warpMax(float v) {
    #pragma unroll
    for (int o = 16; o; o >>= 1) v = fmaxf(v, __shfl_xor_sync(0xffffffffu, v, o));
    return v;
}
__device__ __forceinline__ float warpSum(float v) {
    #pragma unroll
    for (int o = 16; o; o >>= 1) v += __shfl_xor_sync(0xffffffffu, v, o);
    return v;
}

__device__ __forceinline__ void grid_sync() {
    __syncthreads();
    if (threadIdx.x == 0) {
        unsigned int gen = g_bargen;
        __threadfence();                       // release prior phase writes
        if (atomicAdd(&g_barcnt, 1u) == GRID - 1) {
            atomicExch(&g_barcnt, 0u);
            __threadfence();
            g_bargen = gen + 1;
        } else {
            while (g_bargen == gen) __nanosleep(32);
        }
        __threadfence();                       // acquire
    }
    __syncthreads();
}

// ---------------- the whole network in one persistent kernel ------------------
__global__ void __launch_bounds__(BLOCK, 2) gnn_persistent(
    const float* __restrict__ x,  const int* __restrict__ ed,  const float* __restrict__ w,
    const float* __restrict__ W1, const float* __restrict__ b1,
    const float* __restrict__ W2, const float* __restrict__ b2,
    const float* __restrict__ W3, const float* __restrict__ b3,
    const float* __restrict__ A2w, const float* __restrict__ A2b,
    float* __restrict__ out)
{
    __shared__ float sbuf[2080];               // unioned across phases
    __shared__ float sred[33];
    __shared__ float sh16[16];
    const int t = threadIdx.x, b = blockIdx.x;
    const int gtid = b * BLOCK + t;

    // ---- Phase A: init + int64 detection ------------------------------------
    for (int i = gtid; i < N_NODES; i += GSTRIDE) g_dc[i] = (1ull << 24); // self loop
    if (gtid < 16) g_hsum[gtid] = 0.0f;
    if (gtid == 0) {
        int is64 = 1;
        for (int i = 0; i < 64; i++) if (ed[2 * i + 1] != 0) { is64 = 0; break; }
        g_is64 = is64;
    }
    grid_sync();

    // ---- Phase B: edge convert + packed degree atomic, then lin1 ------------
    {
        const int is64 = g_is64;
        if (is64) {
            const long long* e64 = (const long long*)ed;
            for (int e = gtid; e < N_EDGES; e += GSTRIDE) {
                int s = (int)e64[e], d = (int)e64[N_EDGES + e];
                g_src[e] = s; g_dst[e] = d;
                unsigned long long c = (1ull << 40) +
                    (unsigned long long)__float2uint_rn(w[e] * 16777216.0f);
                atomicAdd(&g_dc[d], c);
            }
        } else {
            for (int e = gtid; e < N_EDGES; e += GSTRIDE) {
                int s = ed[e], d = ed[N_EDGES + e];
                g_src[e] = s; g_dst[e] = d;
                unsigned long long c = (1ull << 40) +
                    (unsigned long long)__float2uint_rn(w[e] * 16777216.0f);
                atomicAdd(&g_dc[d], c);
            }
        }
        // lin1: h1 = x @ W1^T   (independent of degree pass)
        float* sW = sbuf;                       // [16][65]
        float* sx = sbuf + 1040;                // [16][65]
        for (int i = t; i < 1024; i += BLOCK) sW[(i >> 6) * 65 + (i & 63)] = W1[i];
        int ni = t >> 4, j = t & 15;
        for (int tile = b; tile < NTILE16; tile += GRID) {
            int node0 = tile * 16;
            __syncthreads();                    // covers sW init + sx reuse
            const float* xb = x + (size_t)node0 * 64;
            for (int i = t; i < 1024; i += BLOCK) sx[(i >> 6) * 65 + (i & 63)] = xb[i];
            __syncthreads();
            float acc = 0.0f;
            #pragma unroll
            for (int k = 0; k < 64; k++) acc = fmaf(sx[ni * 65 + k], sW[j * 65 + k], acc);
            g_h1[(node0 + ni) * 16 + j] = acc;
        }
    }
    grid_sync();

    // ---- Phase C: per-chunk count scan + dinv -------------------------------
    if (b < NCHUNK) {
        int* sc = (int*)sbuf;                  // warp sums sc[0..8]
        int base = b * CHUNK;
        int i0 = base + 2 * t, i1 = i0 + 1;
        int c0 = 0, c1 = 0;
        if (i0 < N_NODES) {
            unsigned long long v = g_dc[i0];
            c0 = (int)(v >> 40);
            g_dinv[i0] = rsqrtf((float)(v & 0xFFFFFFFFFFull) * (1.0f / 16777216.0f));
        }
        if (i1 < N_NODES) {
            unsigned long long v = g_dc[i1];
            c1 = (int)(v >> 40);
            g_dinv[i1] = rsqrtf((float)(v & 0xFFFFFFFFFFull) * (1.0f / 16777216.0f));
        }
        int tsum = c0 + c1;
        int lane = t & 31, wid = t >> 5;
        int v = tsum;
        #pragma unroll
        for (int o = 1; o < 32; o <<= 1) {
            int u = __shfl_up_sync(0xffffffffu, v, o);
            if (lane >= o) v += u;
        }
        if (lane == 31) sc[wid] = v;
        __syncthreads();
        if (t == 0) {
            int run = 0;
            #pragma unroll
            for (int k = 0; k < 8; k++) { int y = sc[k]; sc[k] = run; run += y; }
            g_bsum[b] = run;
        }
        __syncthreads();
        int excl = v - tsum + sc[wid];
        if (i0 < N_NODES) g_off[i0] = excl;
        if (i1 < N_NODES) g_off[i1] = excl + c0;
    }
    grid_sync();

    // ---- Phase D: chunk-offset fixup (redundant per-block prefix) -----------
    if (b < NCHUNK) {
        int off = 0;
        for (int k = 0; k < b; k++) off += g_bsum[k];
        int base = b * CHUNK;
        int lim = min(base + CHUNK, N_NODES);
        for (int i = base + t; i < lim; i += BLOCK) {
            int o = g_off[i] + off;
            g_off[i] = o; g_cur[i] = o;
        }
    }
    if (gtid == 0) g_off[N_NODES] = N_EDGES;
    grid_sync();

    // ---- Phase E: scatter edges into dst buckets ----------------------------
    for (int e = gtid; e < N_EDGES; e += GSTRIDE) {
        int s = g_src[e], d = g_dst[e];
        float nm = g_dinv[s] * w[e] * g_dinv[d];
        int pos = atomicAdd(&g_cur[d], 1);
        g_pk[pos] = make_int2(s, __float_as_int(nm));
    }
    grid_sync();

    // ---- Phase F: agg layer-1 + fused lin2 ----------------------------------
    {
        float* sW = sbuf;                      // [16][17]
        float* sa = sbuf + 272;                // [16][17]
        sW[(t >> 4) * 17 + (t & 15)] = W2[t];
        int ni = t >> 4, f = t & 15;
        float bb = b1[f];
        for (int tile = b; tile < NTILE16; tile += GRID) {
            int node = tile * 16 + ni;
            int beg = g_off[node], end = g_off[node + 1];
            float di = g_dinv[node];
            float acc = di * di * g_h1[node * 16 + f];
            #pragma unroll 4
            for (int i = beg; i < end; i++) {
                int2 p = __ldg(&g_pk[i]);
                acc = fmaf(__int_as_float(p.y), __ldg(&g_h1[(size_t)p.x * 16 + f]), acc);
            }
            __syncthreads();
            sa[ni * 17 + f] = fmaxf(acc + bb, 0.0f);
            __syncthreads();
            float h2 = 0.0f;
            #pragma unroll
            for (int k = 0; k < 16; k++) h2 = fmaf(sa[ni * 17 + k], sW[f * 17 + k], h2);
            g_h2[node * 16 + f] = h2;
        }
    }
    grid_sync();

    // ---- Phase G: agg layer-2 + fused lin3 + hsum ---------------------------
    {
        int ni = t >> 4, f = t & 15;
        float wf = W3[f];
        float bb = b2[f];
        float hloc = 0.0f;
        if (t < 16) sh16[t] = 0.0f;
        __syncthreads();
        for (int tile = b; tile < NTILE16; tile += GRID) {
            int node = tile * 16 + ni;
            int beg = g_off[node], end = g_off[node + 1];
            float di = g_dinv[node];
            float acc = di * di * g_h2[node * 16 + f];
            #pragma unroll 4
            for (int i = beg; i < end; i++) {
                int2 p = __ldg(&g_pk[i]);
                acc = fmaf(__int_as_float(p.y), __ldg(&g_h2[(size_t)p.x * 16 + f]), acc);
            }
            float hv = fmaxf(acc + bb, 0.0f);
            hloc += hv;
            float cv = hv * wf;
            #pragma unroll
            for (int o = 8; o; o >>= 1) cv += __shfl_xor_sync(0xffffffffu, cv, o, 16);
            if (f == 0) g_c[node] = cv;
        }
        atomicAdd(&sh16[f], hloc);
        __syncthreads();
        if (t < 16) atomicAdd(&g_hsum[t], sh16[t]);
    }
    grid_sync();

    // ---- Phase H: agg layer-3 (scalar) + logits + block max -----------------
    {
        float mloc = -3.4e38f;
        int ni = t >> 2, q = t & 3;
        float b3v = b3[0];
        for (int tile = b; tile < NTILE64; tile += GRID) {
            int node = tile * 64 + ni;
            bool valid = node < N_NODES;
            int beg = 0, end = 0;
            if (valid) { beg = g_off[node]; end = g_off[node + 1]; }
            float acc = 0.0f;
            for (int i = beg + q; i < end; i += 4) {
                int2 p = __ldg(&g_pk[i]);
                acc = fmaf(__int_as_float(p.y), __ldg(&g_c[p.x]), acc);
            }
            #pragma unroll
            for (int o = 2; o; o >>= 1) acc += __shfl_xor_sync(0xffffffffu, acc, o, 4);
            if (valid && q == 0) {
                float di = g_dinv[node];
                float lg = b3v + di * di * g_c[node] + acc;
                out[node] = lg;
                mloc = fmaxf(mloc, lg);
            }
        }
        mloc = warpMax(mloc);
        if ((t & 31) == 0) sred[t >> 5] = mloc;
        __syncthreads();
        if (t == 0) {
            float m = sred[0];
            #pragma unroll
            for (int k = 1; k < 8; k++) m = fmaxf(m, sred[k]);
            g_pmax[b] = m;
        }
    }
    grid_sync();

    // ---- Phase I: softmax exp + partial sums + value head -------------------
    {
        float m = -3.4e38f;
        for (int k = t; k < GRID; k += BLOCK) m = fmaxf(m, g_pmax[k]);
        m = warpMax(m);
        if ((t & 31) == 0) sred[t >> 5] = m;
        __syncthreads();
        if (t == 0) {
            float mm = sred[0];
            #pragma unroll
            for (int k = 1; k < 8; k++) mm = fmaxf(mm, sred[k]);
            sred[32] = mm;
        }
        __syncthreads();
        float mx = sred[32];
        float s = 0.0f;
        for (int i = gtid; i < N_NODES; i += GSTRIDE) {
            float e2 = expf(out[i] - mx);
            out[i] = e2;
            s += e2;
        }
        s = warpSum(s);
        if ((t & 31) == 0) sred[t >> 5] = s;
        __syncthreads();
        if (t == 0) {
            float ss = 0.0f;
            #pragma unroll
            for (int k = 0; k < 8; k++) ss += sred[k];
            g_psum[b] = ss;
        }
        if (b == 0 && t == 32) {               // value head (hsum final since Phase G)
            float val = A2b[0];
            const float invn = 1.0f / (float)N_NODES;
            #pragma unroll
            for (int k = 0; k < 16; k++) val += g_hsum[k] * invn * A2w[k];
            out[N_NODES] = val;
        }
    }
    grid_sync();

    // ---- Phase J: normalize -------------------------------------------------
    {
        float s = 0.0f;
        for (int k = t; k < GRID; k += BLOCK) s += g_psum[k];
        s = warpSum(s);
        if ((t & 31) == 0) sred[t >> 5] = s;
        __syncthreads();
        if (t == 0) {
            float ss = 0.0f;
            #pragma unroll
            for (int k = 0; k < 8; k++) ss += sred[k];
            sred[32] = 1.0f / ss;
        }
        __syncthreads();
        float sinv = sred[32];
        for (int i = gtid; i < N_NODES; i += GSTRIDE) out[i] *= sinv;
    }
}

// ---------------- launch ------------------------------------------------------
extern "C" void kernel_launch(void* const* d_in, const int* in_sizes, int n_in,
                              void* d_out, int out_size) {
    const float* x   = (const float*)d_in[0];
    const int*   ed  = (const int*)d_in[1];
    const float* w   = (const float*)d_in[2];
    const float* W1  = (const float*)d_in[3];
    const float* b1  = (const float*)d_in[4];
    const float* W2  = (const float*)d_in[5];
    const float* b2  = (const float*)d_in[6];
    const float* W3  = (const float*)d_in[7];
    const float* b3  = (const float*)d_in[8];
    const float* A2w = (const float*)d_in[9];
    const float* A2b = (const float*)d_in[10];
    float* out = (float*)d_out;

    (void)in_sizes; (void)n_in; (void)out_size;

    gnn_persistent<<<GRID, BLOCK>>>(x, ed, w, W1, b1, W2, b2, W3, b3, A2w, A2b, out);
}

// round 14
// speedup vs baseline: 1.4673x; 1.4673x over previous
#include <cuda_runtime.h>
#include <math.h>

#define N_NODES 100000
#define N_EDGES 3200000
#define GRID    740                 // 148 SMs x 5 resident CTAs
#define BLOCK   256
#define GSTRIDE (GRID * BLOCK)
#define CHUNK   512
#define NCHUNK  ((N_NODES + CHUNK - 1) / CHUNK)   // 196
#define NTILE16 (N_NODES / 16)                    // 6250
#define NTILE64 ((N_NODES + 63) / 64)             // 1563

// ---------------- scratch (device globals) -----------------------------------
__device__ int    g_src[N_EDGES];
__device__ int    g_dst[N_EDGES];
__device__ int2   g_pk[N_EDGES];                 // dst-bucketed {src, norm}
__device__ unsigned long long g_dc[N_NODES];     // packed: cnt<<40 | deg*2^24
__device__ int    g_off[N_NODES + 1];
__device__ int    g_cur[N_NODES];
__device__ int    g_bsum[NCHUNK];
__device__ float  g_dinv[N_NODES];
__device__ float  g_h1[N_NODES * 16];
__device__ float  g_h2[N_NODES * 16];
__device__ float  g_c[N_NODES];
__device__ float  g_hsum[16];
__device__ float  g_pmax[GRID];
__device__ float  g_psum[GRID];
__device__ int    g_is64;
__device__ unsigned int          g_barcnt = 0;
__device__ volatile unsigned int g_bargen = 0;

// ---------------- helpers -----------------------------------------------------
__device__ __forceinline__ float warpMax(float v) {
    #pragma unroll
    for (int o = 16; o; o >>= 1) v = fmaxf(v, __shfl_xor_sync(0xffffffffu, v, o));
    return v;
}
__device__ __forceinline__ float warpSum(float v) {
    #pragma unroll
    for (int o = 16; o; o >>= 1) v += __shfl_xor_sync(0xffffffffu, v, o);
    return v;
}

__device__ __forceinline__ void grid_sync() {
    __syncthreads();
    if (threadIdx.x == 0) {
        unsigned int gen = g_bargen;
        __threadfence();                       // release prior phase writes
        if (atomicAdd(&g_barcnt, 1u) == GRID - 1) {
            atomicExch(&g_barcnt, 0u);
            __threadfence();
            g_bargen = gen + 1;
        } else {
            while (g_bargen == gen) __nanosleep(32);
        }
        __threadfence();                       // acquire
    }
    __syncthreads();
}

// ---------------- the whole network in one persistent kernel ------------------
__global__ void __launch_bounds__(BLOCK, 5) gnn_persistent(
    const float* __restrict__ x,  const int* __restrict__ ed,  const float* __restrict__ w,
    const float* __restrict__ W1, const float* __restrict__ b1,
    const float* __restrict__ W2, const float* __restrict__ b2,
    const float* __restrict__ W3, const float* __restrict__ b3,
    const float* __restrict__ A2w, const float* __restrict__ A2b,
    float* __restrict__ out)
{
    __shared__ float sbuf[2080];               // unioned across phases
    __shared__ float sred[33];
    __shared__ float sh16[16];
    const int t = threadIdx.x, b = blockIdx.x;
    const int gtid = b * BLOCK + t;

    // ---- Phase A: init + int64 detection ------------------------------------
    for (int i = gtid; i < N_NODES; i += GSTRIDE) g_dc[i] = (1ull << 24); // self loop
    if (gtid < 16) g_hsum[gtid] = 0.0f;
    if (gtid == 0) {
        int is64 = 1;
        for (int i = 0; i < 64; i++) if (ed[2 * i + 1] != 0) { is64 = 0; break; }
        g_is64 = is64;
    }
    grid_sync();

    // ---- Phase B: edge convert + packed degree atomic, then lin1 ------------
    {
        const int is64 = g_is64;
        if (is64) {
            const long long* e64 = (const long long*)ed;
            for (int e = gtid; e < N_EDGES; e += 2 * GSTRIDE) {
                int e2 = e + GSTRIDE;
                int s0 = (int)e64[e], d0 = (int)e64[N_EDGES + e];
                float w0 = w[e];
                int s1 = 0, d1 = 0; float w1v = 0.0f;
                bool v1 = e2 < N_EDGES;
                if (v1) { s1 = (int)e64[e2]; d1 = (int)e64[N_EDGES + e2]; w1v = w[e2]; }
                g_src[e] = s0; g_dst[e] = d0;
                atomicAdd(&g_dc[d0], (1ull << 40) +
                    (unsigned long long)__float2uint_rn(w0 * 16777216.0f));
                if (v1) {
                    g_src[e2] = s1; g_dst[e2] = d1;
                    atomicAdd(&g_dc[d1], (1ull << 40) +
                        (unsigned long long)__float2uint_rn(w1v * 16777216.0f));
                }
            }
        } else {
            for (int e = gtid; e < N_EDGES; e += 2 * GSTRIDE) {
                int e2 = e + GSTRIDE;
                int s0 = ed[e], d0 = ed[N_EDGES + e];
                float w0 = w[e];
                int s1 = 0, d1 = 0; float w1v = 0.0f;
                bool v1 = e2 < N_EDGES;
                if (v1) { s1 = ed[e2]; d1 = ed[N_EDGES + e2]; w1v = w[e2]; }
                g_src[e] = s0; g_dst[e] = d0;
                atomicAdd(&g_dc[d0], (1ull << 40) +
                    (unsigned long long)__float2uint_rn(w0 * 16777216.0f));
                if (v1) {
                    g_src[e2] = s1; g_dst[e2] = d1;
                    atomicAdd(&g_dc[d1], (1ull << 40) +
                        (unsigned long long)__float2uint_rn(w1v * 16777216.0f));
                }
            }
        }
        // lin1: h1 = x @ W1^T   (independent of degree pass)
        float* sW = sbuf;                       // [16][65]
        float* sx = sbuf + 1040;                // [16][65]
        for (int i = t; i < 1024; i += BLOCK) sW[(i >> 6) * 65 + (i & 63)] = W1[i];
        int ni = t >> 4, j = t & 15;
        for (int tile = b; tile < NTILE16; tile += GRID) {
            int node0 = tile * 16;
            __syncthreads();                    // covers sW init + sx reuse
            const float* xb = x + (size_t)node0 * 64;
            for (int i = t; i < 1024; i += BLOCK) sx[(i >> 6) * 65 + (i & 63)] = xb[i];
            __syncthreads();
            float acc = 0.0f;
            #pragma unroll
            for (int k = 0; k < 64; k++) acc = fmaf(sx[ni * 65 + k], sW[j * 65 + k], acc);
            g_h1[(node0 + ni) * 16 + j] = acc;
        }
    }
    grid_sync();

    // ---- Phase C: per-chunk count scan + dinv -------------------------------
    if (b < NCHUNK) {
        int* sc = (int*)sbuf;                  // warp sums sc[0..8]
        int base = b * CHUNK;
        int i0 = base + 2 * t, i1 = i0 + 1;
        int c0 = 0, c1 = 0;
        if (i0 < N_NODES) {
            unsigned long long v = g_dc[i0];
            c0 = (int)(v >> 40);
            g_dinv[i0] = rsqrtf((float)(v & 0xFFFFFFFFFFull) * (1.0f / 16777216.0f));
        }
        if (i1 < N_NODES) {
            unsigned long long v = g_dc[i1];
            c1 = (int)(v >> 40);
            g_dinv[i1] = rsqrtf((float)(v & 0xFFFFFFFFFFull) * (1.0f / 16777216.0f));
        }
        int tsum = c0 + c1;
        int lane = t & 31, wid = t >> 5;
        int v = tsum;
        #pragma unroll
        for (int o = 1; o < 32; o <<= 1) {
            int u = __shfl_up_sync(0xffffffffu, v, o);
            if (lane >= o) v += u;
        }
        if (lane == 31) sc[wid] = v;
        __syncthreads();
        if (t == 0) {
            int run = 0;
            #pragma unroll
            for (int k = 0; k < 8; k++) { int y = sc[k]; sc[k] = run; run += y; }
            g_bsum[b] = run;
        }
        __syncthreads();
        int excl = v - tsum + sc[wid];
        if (i0 < N_NODES) g_off[i0] = excl;
        if (i1 < N_NODES) g_off[i1] = excl + c0;
    }
    grid_sync();

    // ---- Phase D: chunk-offset fixup (redundant per-block prefix) -----------
    if (b < NCHUNK) {
        int off = 0;
        for (int k = 0; k < b; k++) off += g_bsum[k];
        int base = b * CHUNK;
        int lim = min(base + CHUNK, N_NODES);
        for (int i = base + t; i < lim; i += BLOCK) {
            int o = g_off[i] + off;
            g_off[i] = o; g_cur[i] = o;
        }
    }
    if (gtid == 0) g_off[N_NODES] = N_EDGES;
    grid_sync();

    // ---- Phase E: scatter edges into dst buckets ----------------------------
    for (int e = gtid; e < N_EDGES; e += 2 * GSTRIDE) {
        int e2 = e + GSTRIDE;
        int s0 = g_src[e], d0 = g_dst[e];
        float n0 = g_dinv[s0] * w[e] * g_dinv[d0];
        bool v1 = e2 < N_EDGES;
        int s1 = 0, d1 = 0; float n1 = 0.0f;
        if (v1) {
            s1 = g_src[e2]; d1 = g_dst[e2];
            n1 = g_dinv[s1] * w[e2] * g_dinv[d1];
        }
        int p0 = atomicAdd(&g_cur[d0], 1);
        g_pk[p0] = make_int2(s0, __float_as_int(n0));
        if (v1) {
            int p1 = atomicAdd(&g_cur[d1], 1);
            g_pk[p1] = make_int2(s1, __float_as_int(n1));
        }
    }
    grid_sync();

    // ---- Phase F: agg layer-1 + fused lin2 ----------------------------------
    {
        float* sW = sbuf;                      // [16][17]
        float* sa = sbuf + 272;                // [16][17]
        sW[(t >> 4) * 17 + (t & 15)] = W2[t];
        int ni = t >> 4, f = t & 15;
        float bb = b1[f];
        for (int tile = b; tile < NTILE16; tile += GRID) {
            int node = tile * 16 + ni;
            int beg = g_off[node], end = g_off[node + 1];
            float a0 = 0.0f, a1 = 0.0f, a2 = 0.0f, a3 = 0.0f;
            int i = beg;
            for (; i + 3 < end; i += 4) {
                int2 p0 = __ldg(&g_pk[i]);
                int2 p1 = __ldg(&g_pk[i + 1]);
                int2 p2 = __ldg(&g_pk[i + 2]);
                int2 p3 = __ldg(&g_pk[i + 3]);
                a0 = fmaf(__int_as_float(p0.y), __ldg(&g_h1[(size_t)p0.x * 16 + f]), a0);
                a1 = fmaf(__int_as_float(p1.y), __ldg(&g_h1[(size_t)p1.x * 16 + f]), a1);
                a2 = fmaf(__int_as_float(p2.y), __ldg(&g_h1[(size_t)p2.x * 16 + f]), a2);
                a3 = fmaf(__int_as_float(p3.y), __ldg(&g_h1[(size_t)p3.x * 16 + f]), a3);
            }
            for (; i < end; i++) {
                int2 p = __ldg(&g_pk[i]);
                a0 = fmaf(__int_as_float(p.y), __ldg(&g_h1[(size_t)p.x * 16 + f]), a0);
            }
            float di = g_dinv[node];
            float acc = di * di * g_h1[node * 16 + f] + ((a0 + a1) + (a2 + a3));
            __syncthreads();
            sa[ni * 17 + f] = fmaxf(acc + bb, 0.0f);
            __syncthreads();
            float h2 = 0.0f;
            #pragma unroll
            for (int k = 0; k < 16; k++) h2 = fmaf(sa[ni * 17 + k], sW[f * 17 + k], h2);
            g_h2[node * 16 + f] = h2;
        }
    }
    grid_sync();

    // ---- Phase G: agg layer-2 + fused lin3 + hsum ---------------------------
    {
        int ni = t >> 4, f = t & 15;
        float wf = W3[f];
        float bb = b2[f];
        float hloc = 0.0f;
        if (t < 16) sh16[t] = 0.0f;
        __syncthreads();
        for (int tile = b; tile < NTILE16; tile += GRID) {
            int node = tile * 16 + ni;
            int beg = g_off[node], end = g_off[node + 1];
            float a0 = 0.0f, a1 = 0.0f, a2 = 0.0f, a3 = 0.0f;
            int i = beg;
            for (; i + 3 < end; i += 4) {
                int2 p0 = __ldg(&g_pk[i]);
                int2 p1 = __ldg(&g_pk[i + 1]);
                int2 p2 = __ldg(&g_pk[i + 2]);
                int2 p3 = __ldg(&g_pk[i + 3]);
                a0 = fmaf(__int_as_float(p0.y), __ldg(&g_h2[(size_t)p0.x * 16 + f]), a0);
                a1 = fmaf(__int_as_float(p1.y), __ldg(&g_h2[(size_t)p1.x * 16 + f]), a1);
                a2 = fmaf(__int_as_float(p2.y), __ldg(&g_h2[(size_t)p2.x * 16 + f]), a2);
                a3 = fmaf(__int_as_float(p3.y), __ldg(&g_h2[(size_t)p3.x * 16 + f]), a3);
            }
            for (; i < end; i++) {
                int2 p = __ldg(&g_pk[i]);
                a0 = fmaf(__int_as_float(p.y), __ldg(&g_h2[(size_t)p.x * 16 + f]), a0);
            }
            float di = g_dinv[node];
            float acc = di * di * g_h2[node * 16 + f] + ((a0 + a1) + (a2 + a3));
            float hv = fmaxf(acc + bb, 0.0f);
            hloc += hv;
            float cv = hv * wf;
            #pragma unroll
            for (int o = 8; o; o >>= 1) cv += __shfl_xor_sync(0xffffffffu, cv, o, 16);
            if (f == 0) g_c[node] = cv;
        }
        atomicAdd(&sh16[f], hloc);
        __syncthreads();
        if (t < 16) atomicAdd(&g_hsum[t], sh16[t]);
    }
    grid_sync();

    // ---- Phase H: agg layer-3 (scalar) + logits + block max -----------------
    {
        float mloc = -3.4e38f;
        int ni = t >> 2, q = t & 3;
        float b3v = b3[0];
        for (int tile = b; tile < NTILE64; tile += GRID) {
            int node = tile * 64 + ni;
            bool valid = node < N_NODES;
            int beg = 0, end = 0;
            if (valid) { beg = g_off[node]; end = g_off[node + 1]; }
            float a0 = 0.0f, a1 = 0.0f;
            int i = beg + q;
            for (; i + 4 < end; i += 8) {
                int2 p0 = __ldg(&g_pk[i]);
                int2 p1 = __ldg(&g_pk[i + 4]);
                a0 = fmaf(__int_as_float(p0.y), __ldg(&g_c[p0.x]), a0);
                a1 = fmaf(__int_as_float(p1.y), __ldg(&g_c[p1.x]), a1);
            }
            if (i < end) {
                int2 p = __ldg(&g_pk[i]);
                a0 = fmaf(__int_as_float(p.y), __ldg(&g_c[p.x]), a0);
            }
            float acc = a0 + a1;
            #pragma unroll
            for (int o = 2; o; o >>= 1) acc += __shfl_xor_sync(0xffffffffu, acc, o, 4);
            if (valid && q == 0) {
                float di = g_dinv[node];
                float lg = b3v + di * di * g_c[node] + acc;
                out[node] = lg;
                mloc = fmaxf(mloc, lg);
            }
        }
        mloc = warpMax(mloc);
        if ((t & 31) == 0) sred[t >> 5] = mloc;
        __syncthreads();
        if (t == 0) {
            float m = sred[0];
            #pragma unroll
            for (int k = 1; k < 8; k++) m = fmaxf(m, sred[k]);
            g_pmax[b] = m;
        }
    }
    grid_sync();

    // ---- Phase I: softmax exp + partial sums + value head -------------------
    {
        float m = -3.4e38f;
        for (int k = t; k < GRID; k += BLOCK) m = fmaxf(m, g_pmax[k]);
        m = warpMax(m);
        if ((t & 31) == 0) sred[t >> 5] = m;
        __syncthreads();
        if (t == 0) {
            float mm = sred[0];
            #pragma unroll
            for (int k = 1; k < 8; k++) mm = fmaxf(mm, sred[k]);
            sred[32] = mm;
        }
        __syncthreads();
        float mx = sred[32];
        float s = 0.0f;
        for (int i = gtid; i < N_NODES; i += GSTRIDE) {
            float e2 = expf(out[i] - mx);
            out[i] = e2;
            s += e2;
        }
        s = warpSum(s);
        if ((t & 31) == 0) sred[t >> 5] = s;
        __syncthreads();
        if (t == 0) {
            float ss = 0.0f;
            #pragma unroll
            for (int k = 0; k < 8; k++) ss += sred[k];
            g_psum[b] = ss;
        }
        if (b == 0 && t == 32) {               // value head (hsum final since Phase G)
            float val = A2b[0];
            const float invn = 1.0f / (float)N_NODES;
            #pragma unroll
            for (int k = 0; k < 16; k++) val += g_hsum[k] * invn * A2w[k];
            out[N_NODES] = val;
        }
    }
    grid_sync();

    // ---- Phase J: normalize -------------------------------------------------
    {
        float s = 0.0f;
        for (int k = t; k < GRID; k += BLOCK) s += g_psum[k];
        s = warpSum(s);
        if ((t & 31) == 0) sred[t >> 5] = s;
        __syncthreads();
        if (t == 0) {
            float ss = 0.0f;
            #pragma unroll
            for (int k = 0; k < 8; k++) ss += sred[k];
            sred[32] = 1.0f / ss;
        }
        __syncthreads();
        float sinv = sred[32];
        for (int i = gtid; i < N_NODES; i += GSTRIDE) out[i] *= sinv;
    }
}

// ---------------- launch ------------------------------------------------------
extern "C" void kernel_launch(void* const* d_in, const int* in_sizes, int n_in,
                              void* d_out, int out_size) {
    const float* x   = (const float*)d_in[0];
    const int*   ed  = (const int*)d_in[1];
    const float* w   = (const float*)d_in[2];
    const float* W1  = (const float*)d_in[3];
    const float* b1  = (const float*)d_in[4];
    const float* W2  = (const float*)d_in[5];
    const float* b2  = (const float*)d_in[6];
    const float* W3  = (const float*)d_in[7];
    const float* b3  = (const float*)d_in[8];
    const float* A2w = (const float*)d_in[9];
    const float* A2b = (const float*)d_in[10];
    float* out = (float*)d_out;

    (void)in_sizes; (void)n_in; (void)out_size;

    gnn_persistent<<<GRID, BLOCK>>>(x, ed, w, W1, b1, W2, b2, W3, b3, A2w, A2b, out);
}

// round 15
// speedup vs baseline: 1.4788x; 1.0078x over previous
#include <cuda_runtime.h>
#include <math.h>

#define N_NODES 100000
#define N_EDGES 3200000
#define GRID    740                 // 148 SMs x 5 resident CTAs
#define BLOCK   256
#define GSTRIDE (GRID * BLOCK)
#define CHUNK   512
#define NCHUNK  ((N_NODES + CHUNK - 1) / CHUNK)   // 196
#define NTILE16 (N_NODES / 16)                    // 6250
#define NTILE64 ((N_NODES + 63) / 64)             // 1563

// ---------------- scratch (device globals) -----------------------------------
__device__ int    g_src[N_EDGES];
__device__ int    g_dst[N_EDGES];
__device__ int2   g_pk[N_EDGES];                 // dst-bucketed {src, norm}
__device__ unsigned long long g_dc[N_NODES];     // packed: cnt<<40 | deg*2^24
__device__ int    g_off[N_NODES + 1];
__device__ int    g_cur[N_NODES];
__device__ int    g_bsum[NCHUNK];
__device__ float  g_dinv[N_NODES];
__device__ float  g_h1[N_NODES * 16];
__device__ float  g_h2[N_NODES * 16];
__device__ float  g_c[N_NODES];
__device__ float  g_hsum[16];
__device__ float  g_pmax[GRID];
__device__ float  g_psum[GRID];
__device__ int    g_is64;
__device__ unsigned int          g_barcnt = 0;
__device__ volatile unsigned int g_bargen = 0;

// ---------------- helpers -----------------------------------------------------
__device__ __forceinline__ float warpMax(float v) {
    #pragma unroll
    for (int o = 16; o; o >>= 1) v = fmaxf(v, __shfl_xor_sync(0xffffffffu, v, o));
    return v;
}
__device__ __forceinline__ float warpSum(float v) {
    #pragma unroll
    for (int o = 16; o; o >>= 1) v += __shfl_xor_sync(0xffffffffu, v, o);
    return v;
}

__device__ __forceinline__ void grid_sync() {
    __syncthreads();
    if (threadIdx.x == 0) {
        unsigned int gen = g_bargen;
        __threadfence();                       // release prior phase writes
        if (atomicAdd(&g_barcnt, 1u) == GRID - 1) {
            atomicExch(&g_barcnt, 0u);
            __threadfence();
            g_bargen = gen + 1;
        } else {
            while (g_bargen == gen) __nanosleep(32);
        }
        __threadfence();                       // acquire
    }
    __syncthreads();
}

// ---------------- the whole network in one persistent kernel ------------------
__global__ void __launch_bounds__(BLOCK, 5) gnn_persistent(
    const float* __restrict__ x,  const int* __restrict__ ed,  const float* __restrict__ w,
    const float* __restrict__ W1, const float* __restrict__ b1,
    const float* __restrict__ W2, const float* __restrict__ b2,
    const float* __restrict__ W3, const float* __restrict__ b3,
    const float* __restrict__ A2w, const float* __restrict__ A2b,
    float* __restrict__ out)
{
    __shared__ float sbuf[2080];               // unioned across phases
    __shared__ float sred[33];
    __shared__ float sh16[16];
    const int t = threadIdx.x, b = blockIdx.x;
    const int gtid = b * BLOCK + t;

    // ---- Phase A: init + int64 detection ------------------------------------
    for (int i = gtid; i < N_NODES; i += GSTRIDE) g_dc[i] = (1ull << 24); // self loop
    if (gtid < 16) g_hsum[gtid] = 0.0f;
    if (gtid == 0) {
        int is64 = 1;
        for (int i = 0; i < 64; i++) if (ed[2 * i + 1] != 0) { is64 = 0; break; }
        g_is64 = is64;
    }
    grid_sync();

    // ---- Phase B: edge convert + packed degree atomic, then lin1 ------------
    {
        const int is64 = g_is64;
        if (is64) {
            const long long* e64 = (const long long*)ed;
            for (int e = gtid; e < N_EDGES; e += 2 * GSTRIDE) {
                int e2 = e + GSTRIDE;
                int s0 = (int)e64[e], d0 = (int)e64[N_EDGES + e];
                float w0 = w[e];
                int s1 = 0, d1 = 0; float w1v = 0.0f;
                bool v1 = e2 < N_EDGES;
                if (v1) { s1 = (int)e64[e2]; d1 = (int)e64[N_EDGES + e2]; w1v = w[e2]; }
                g_src[e] = s0; g_dst[e] = d0;
                atomicAdd(&g_dc[d0], (1ull << 40) +
                    (unsigned long long)__float2uint_rn(w0 * 16777216.0f));
                if (v1) {
                    g_src[e2] = s1; g_dst[e2] = d1;
                    atomicAdd(&g_dc[d1], (1ull << 40) +
                        (unsigned long long)__float2uint_rn(w1v * 16777216.0f));
                }
            }
        } else {
            for (int e = gtid; e < N_EDGES; e += 2 * GSTRIDE) {
                int e2 = e + GSTRIDE;
                int s0 = ed[e], d0 = ed[N_EDGES + e];
                float w0 = w[e];
                int s1 = 0, d1 = 0; float w1v = 0.0f;
                bool v1 = e2 < N_EDGES;
                if (v1) { s1 = ed[e2]; d1 = ed[N_EDGES + e2]; w1v = w[e2]; }
                g_src[e] = s0; g_dst[e] = d0;
                atomicAdd(&g_dc[d0], (1ull << 40) +
                    (unsigned long long)__float2uint_rn(w0 * 16777216.0f));
                if (v1) {
                    g_src[e2] = s1; g_dst[e2] = d1;
                    atomicAdd(&g_dc[d1], (1ull << 40) +
                        (unsigned long long)__float2uint_rn(w1v * 16777216.0f));
                }
            }
        }
        // lin1: h1 = x @ W1^T   (independent of degree pass)
        float* sW = sbuf;                       // [16][65]
        float* sx = sbuf + 1040;                // [16][65]
        for (int i = t; i < 1024; i += BLOCK) sW[(i >> 6) * 65 + (i & 63)] = W1[i];
        int ni = t >> 4, j = t & 15;
        for (int tile = b; tile < NTILE16; tile += GRID) {
            int node0 = tile * 16;
            __syncthreads();                    // covers sW init + sx reuse
            const float* xb = x + (size_t)node0 * 64;
            for (int i = t; i < 1024; i += BLOCK) sx[(i >> 6) * 65 + (i & 63)] = xb[i];
            __syncthreads();
            float acc = 0.0f;
            #pragma unroll
            for (int k = 0; k < 64; k++) acc = fmaf(sx[ni * 65 + k], sW[j * 65 + k], acc);
            g_h1[(node0 + ni) * 16 + j] = acc;
        }
    }
    grid_sync();

    // ---- Phase C: per-chunk count scan + dinv -------------------------------
    if (b < NCHUNK) {
        int* sc = (int*)sbuf;                  // warp sums sc[0..8]
        int base = b * CHUNK;
        int i0 = base + 2 * t, i1 = i0 + 1;
        int c0 = 0, c1 = 0;
        if (i0 < N_NODES) {
            unsigned long long v = g_dc[i0];
            c0 = (int)(v >> 40);
            g_dinv[i0] = rsqrtf((float)(v & 0xFFFFFFFFFFull) * (1.0f / 16777216.0f));
        }
        if (i1 < N_NODES) {
            unsigned long long v = g_dc[i1];
            c1 = (int)(v >> 40);
            g_dinv[i1] = rsqrtf((float)(v & 0xFFFFFFFFFFull) * (1.0f / 16777216.0f));
        }
        int tsum = c0 + c1;
        int lane = t & 31, wid = t >> 5;
        int v = tsum;
        #pragma unroll
        for (int o = 1; o < 32; o <<= 1) {
            int u = __shfl_up_sync(0xffffffffu, v, o);
            if (lane >= o) v += u;
        }
        if (lane == 31) sc[wid] = v;
        __syncthreads();
        if (t == 0) {
            int run = 0;
            #pragma unroll
            for (int k = 0; k < 8; k++) { int y = sc[k]; sc[k] = run; run += y; }
            g_bsum[b] = run;
        }
        __syncthreads();
        int excl = v - tsum + sc[wid];
        if (i0 < N_NODES) g_off[i0] = excl;
        if (i1 < N_NODES) g_off[i1] = excl + c0;
    }
    grid_sync();

    // ---- Phase D: chunk-offset fixup (redundant per-block prefix) -----------
    if (b < NCHUNK) {
        int off = 0;
        for (int k = 0; k < b; k++) off += g_bsum[k];
        int base = b * CHUNK;
        int lim = min(base + CHUNK, N_NODES);
        for (int i = base + t; i < lim; i += BLOCK) {
            int o = g_off[i] + off;
            g_off[i] = o; g_cur[i] = o;
        }
    }
    if (gtid == 0) g_off[N_NODES] = N_EDGES;
    grid_sync();

    // ---- Phase E: scatter edges into dst buckets ----------------------------
    for (int e = gtid; e < N_EDGES; e += 2 * GSTRIDE) {
        int e2 = e + GSTRIDE;
        int s0 = g_src[e], d0 = g_dst[e];
        float n0 = g_dinv[s0] * w[e] * g_dinv[d0];
        bool v1 = e2 < N_EDGES;
        int s1 = 0, d1 = 0; float n1 = 0.0f;
        if (v1) {
            s1 = g_src[e2]; d1 = g_dst[e2];
            n1 = g_dinv[s1] * w[e2] * g_dinv[d1];
        }
        int p0 = atomicAdd(&g_cur[d0], 1);
        g_pk[p0] = make_int2(s0, __float_as_int(n0));
        if (v1) {
            int p1 = atomicAdd(&g_cur[d1], 1);
            g_pk[p1] = make_int2(s1, __float_as_int(n1));
        }
    }
    grid_sync();

    // ---- Phase F: agg layer-1 + fused lin2 ----------------------------------
    {
        float* sW = sbuf;                      // [16][17]
        float* sa = sbuf + 272;                // [16][17]
        sW[(t >> 4) * 17 + (t & 15)] = W2[t];
        int ni = t >> 4, f = t & 15;
        float bb = b1[f];
        for (int tile = b; tile < NTILE16; tile += GRID) {
            int node = tile * 16 + ni;
            int beg = g_off[node], end = g_off[node + 1];
            float a0 = 0.0f, a1 = 0.0f, a2 = 0.0f, a3 = 0.0f;
            int i = beg;
            for (; i + 3 < end; i += 4) {
                int2 p0 = __ldg(&g_pk[i]);
                int2 p1 = __ldg(&g_pk[i + 1]);
                int2 p2 = __ldg(&g_pk[i + 2]);
                int2 p3 = __ldg(&g_pk[i + 3]);
                a0 = fmaf(__int_as_float(p0.y), __ldg(&g_h1[(size_t)p0.x * 16 + f]), a0);
                a1 = fmaf(__int_as_float(p1.y), __ldg(&g_h1[(size_t)p1.x * 16 + f]), a1);
                a2 = fmaf(__int_as_float(p2.y), __ldg(&g_h1[(size_t)p2.x * 16 + f]), a2);
                a3 = fmaf(__int_as_float(p3.y), __ldg(&g_h1[(size_t)p3.x * 16 + f]), a3);
            }
            for (; i < end; i++) {
                int2 p = __ldg(&g_pk[i]);
                a0 = fmaf(__int_as_float(p.y), __ldg(&g_h1[(size_t)p.x * 16 + f]), a0);
            }
            float di = g_dinv[node];
            float acc = di * di * g_h1[node * 16 + f] + ((a0 + a1) + (a2 + a3));
            __syncthreads();
            sa[ni * 17 + f] = fmaxf(acc + bb, 0.0f);
            __syncthreads();
            float h2 = 0.0f;
            #pragma unroll
            for (int k = 0; k < 16; k++) h2 = fmaf(sa[ni * 17 + k], sW[f * 17 + k], h2);
            g_h2[node * 16 + f] = h2;
        }
    }
    grid_sync();

    // ---- Phase G: agg layer-2 + fused lin3 + hsum ---------------------------
    {
        int ni = t >> 4, f = t & 15;
        float wf = W3[f];
        float bb = b2[f];
        float hloc = 0.0f;
        if (t < 16) sh16[t] = 0.0f;
        __syncthreads();
        for (int tile = b; tile < NTILE16; tile += GRID) {
            int node = tile * 16 + ni;
            int beg = g_off[node], end = g_off[node + 1];
            float a0 = 0.0f, a1 = 0.0f, a2 = 0.0f, a3 = 0.0f;
            int i = beg;
            for (; i + 3 < end; i += 4) {
                int2 p0 = __ldg(&g_pk[i]);
                int2 p1 = __ldg(&g_pk[i + 1]);
                int2 p2 = __ldg(&g_pk[i + 2]);
                int2 p3 = __ldg(&g_pk[i + 3]);
                a0 = fmaf(__int_as_float(p0.y), __ldg(&g_h2[(size_t)p0.x * 16 + f]), a0);
                a1 = fmaf(__int_as_float(p1.y), __ldg(&g_h2[(size_t)p1.x * 16 + f]), a1);
                a2 = fmaf(__int_as_float(p2.y), __ldg(&g_h2[(size_t)p2.x * 16 + f]), a2);
                a3 = fmaf(__int_as_float(p3.y), __ldg(&g_h2[(size_t)p3.x * 16 + f]), a3);
            }
            for (; i < end; i++) {
                int2 p = __ldg(&g_pk[i]);
                a0 = fmaf(__int_as_float(p.y), __ldg(&g_h2[(size_t)p.x * 16 + f]), a0);
            }
            float di = g_dinv[node];
            float acc = di * di * g_h2[node * 16 + f] + ((a0 + a1) + (a2 + a3));
            float hv = fmaxf(acc + bb, 0.0f);
            hloc += hv;
            float cv = hv * wf;
            #pragma unroll
            for (int o = 8; o; o >>= 1) cv += __shfl_xor_sync(0xffffffffu, cv, o, 16);
            if (f == 0) g_c[node] = cv;
        }
        atomicAdd(&sh16[f], hloc);
        __syncthreads();
        if (t < 16) atomicAdd(&g_hsum[t], sh16[t]);
    }
    grid_sync();

    // ---- Phase H: agg layer-3 (scalar) + logits + block max -----------------
    {
        float mloc = -3.4e38f;
        int ni = t >> 2, q = t & 3;
        float b3v = b3[0];
        for (int tile = b; tile < NTILE64; tile += GRID) {
            int node = tile * 64 + ni;
            bool valid = node < N_NODES;
            int beg = 0, end = 0;
            if (valid) { beg = g_off[node]; end = g_off[node + 1]; }
            float a0 = 0.0f, a1 = 0.0f;
            int i = beg + q;
            for (; i + 4 < end; i += 8) {
                int2 p0 = __ldg(&g_pk[i]);
                int2 p1 = __ldg(&g_pk[i + 4]);
                a0 = fmaf(__int_as_float(p0.y), __ldg(&g_c[p0.x]), a0);
                a1 = fmaf(__int_as_float(p1.y), __ldg(&g_c[p1.x]), a1);
            }
            if (i < end) {
                int2 p = __ldg(&g_pk[i]);
                a0 = fmaf(__int_as_float(p.y), __ldg(&g_c[p.x]), a0);
            }
            float acc = a0 + a1;
            #pragma unroll
            for (int o = 2; o; o >>= 1) acc += __shfl_xor_sync(0xffffffffu, acc, o, 4);
            if (valid && q == 0) {
                float di = g_dinv[node];
                float lg = b3v + di * di * g_c[node] + acc;
                out[node] = lg;
                mloc = fmaxf(mloc, lg);
            }
        }
        mloc = warpMax(mloc);
        if ((t & 31) == 0) sred[t >> 5] = mloc;
        __syncthreads();
        if (t == 0) {
            float m = sred[0];
            #pragma unroll
            for (int k = 1; k < 8; k++) m = fmaxf(m, sred[k]);
            g_pmax[b] = m;
        }
    }
    grid_sync();

    // ---- Phase I: softmax exp + partial sums + value head -------------------
    {
        float m = -3.4e38f;
        for (int k = t; k < GRID; k += BLOCK) m = fmaxf(m, g_pmax[k]);
        m = warpMax(m);
        if ((t & 31) == 0) sred[t >> 5] = m;
        __syncthreads();
        if (t == 0) {
            float mm = sred[0];
            #pragma unroll
            for (int k = 1; k < 8; k++) mm = fmaxf(mm, sred[k]);
            sred[32] = mm;
        }
        __syncthreads();
        float mx = sred[32];
        float s = 0.0f;
        for (int i = gtid; i < N_NODES; i += GSTRIDE) {
            float e2 = expf(out[i] - mx);
            out[i] = e2;
            s += e2;
        }
        s = warpSum(s);
        if ((t & 31) == 0) sred[t >> 5] = s;
        __syncthreads();
        if (t == 0) {
            float ss = 0.0f;
            #pragma unroll
            for (int k = 0; k < 8; k++) ss += sred[k];
            g_psum[b] = ss;
        }
        if (b == 0 && t == 32) {               // value head (hsum final since Phase G)
            float val = A2b[0];
            const float invn = 1.0f / (float)N_NODES;
            #pragma unroll
            for (int k = 0; k < 16; k++) val += g_hsum[k] * invn * A2w[k];
            out[N_NODES] = val;
        }
    }
    grid_sync();

    // ---- Phase J: normalize -------------------------------------------------
    {
        float s = 0.0f;
        for (int k = t; k < GRID; k += BLOCK) s += g_psum[k];
        s = warpSum(s);
        if ((t & 31) == 0) sred[t >> 5] = s;
        __syncthreads();
        if (t == 0) {
            float ss = 0.0f;
            #pragma unroll
            for (int k = 0; k < 8; k++) ss += sred[k];
            sred[32] = 1.0f / ss;
        }
        __syncthreads();
        float sinv = sred[32];
        for (int i = gtid; i < N_NODES; i += GSTRIDE) out[i] *= sinv;
    }
}

// ---------------- launch ------------------------------------------------------
extern "C" void kernel_launch(void* const* d_in, const int* in_sizes, int n_in,
                              void* d_out, int out_size) {
    const float* x   = (const float*)d_in[0];
    const int*   ed  = (const int*)d_in[1];
    const float* w   = (const float*)d_in[2];
    const float* W1  = (const float*)d_in[3];
    const float* b1  = (const float*)d_in[4];
    const float* W2  = (const float*)d_in[5];
    const float* b2  = (const float*)d_in[6];
    const float* W3  = (const float*)d_in[7];
    const float* b3  = (const float*)d_in[8];
    const float* A2w = (const float*)d_in[9];
    const float* A2b = (const float*)d_in[10];
    float* out = (float*)d_out;

    (void)in_sizes; (void)n_in; (void)out_size;

    gnn_persistent<<<GRID, BLOCK>>>(x, ed, w, W1, b1, W2, b2, W3, b3, A2w, A2b, out);
}

// round 16
// speedup vs baseline: 1.7386x; 1.1757x over previous
#include <cuda_runtime.h>
#include <math.h>

#define N_NODES 100000
#define N_EDGES 3200000
#define HALF_E  (N_EDGES / 2)
#define N_BLK   391                       // ceil(N_NODES/256)
#define NTILE16 (N_NODES / 16)            // 6250
#define NTILE64 ((N_NODES + 63) / 64)     // 1563

// ---------------- scratch (device globals) -----------------------------------
__device__ int    g_src[N_EDGES];
__device__ int    g_dst[N_EDGES];
__device__ int2   g_pk[N_EDGES];                 // dst-bucketed {src, norm}
__device__ unsigned long long g_dc[N_NODES];     // packed: cnt<<40 | deg*2^24
__device__ int    g_off[N_NODES + 1];
__device__ int    g_cur[N_NODES];
__device__ int    g_bsum[N_BLK];
__device__ int    g_bscan[N_BLK];
__device__ float  g_dinv[N_NODES];
__device__ float  g_h1[N_NODES * 16];
__device__ float  g_h2[N_NODES * 16];
__device__ float  g_c[N_NODES];
__device__ float  g_hsum[16];
__device__ float  g_pmax[NTILE64];
__device__ float  g_part[256];
__device__ float  g_smax;
__device__ float  g_sinv;
__device__ int    g_is64;

// ---------------- helpers -----------------------------------------------------
__device__ __forceinline__ float warpMax(float v) {
    #pragma unroll
    for (int o = 16; o; o >>= 1) v = fmaxf(v, __shfl_xor_sync(0xffffffffu, v, o));
    return v;
}
__device__ __forceinline__ float warpSum(float v) {
    #pragma unroll
    for (int o = 16; o; o >>= 1) v += __shfl_xor_sync(0xffffffffu, v, o);
    return v;
}

// ---------------- prep --------------------------------------------------------
__global__ void k_init(const int* __restrict__ ed) {
    int i = blockIdx.x * blockDim.x + threadIdx.x;
    if (i < N_NODES) g_dc[i] = (1ull << 24);     // self-loop weight 1.0
    if (i < 16)      g_hsum[i] = 0.0f;
    if (i == 0) {
        int is64 = 1;
        for (int k = 0; k < 64; k++) if (ed[2 * k + 1] != 0) { is64 = 0; break; }
        g_is64 = is64;
    }
}

// edge convert + packed degree/count atomic; 2 edges per thread (strided halves)
__global__ void k_deg(const int* __restrict__ ed, const float* __restrict__ w) {
    int e0 = blockIdx.x * blockDim.x + threadIdx.x;
    int e1 = e0 + HALF_E;
    int s0, d0, s1, d1;
    if (g_is64) {
        const long long* e64 = (const long long*)ed;
        s0 = (int)e64[e0]; d0 = (int)e64[N_EDGES + e0];
        s1 = (int)e64[e1]; d1 = (int)e64[N_EDGES + e1];
    } else {
        s0 = ed[e0]; d0 = ed[N_EDGES + e0];
        s1 = ed[e1]; d1 = ed[N_EDGES + e1];
    }
    float w0 = w[e0], w1 = w[e1];
    g_src[e0] = s0; g_dst[e0] = d0;
    g_src[e1] = s1; g_dst[e1] = d1;
    atomicAdd(&g_dc[d0], (1ull << 40) +
        (unsigned long long)__float2uint_rn(w0 * 16777216.0f));
    atomicAdd(&g_dc[d1], (1ull << 40) +
        (unsigned long long)__float2uint_rn(w1 * 16777216.0f));
}

// per-256-node chunk scan of counts + fused dinv
__global__ void k_scan1() {
    __shared__ int sc[8];
    int t = threadIdx.x;
    int i = blockIdx.x * 256 + t;
    int c = 0;
    if (i < N_NODES) {
        unsigned long long v = g_dc[i];
        c = (int)(v >> 40);
        g_dinv[i] = rsqrtf((float)(v & 0xFFFFFFFFFFull) * (1.0f / 16777216.0f));
    }
    int lane = t & 31, wid = t >> 5;
    int v = c;
    #pragma unroll
    for (int o = 1; o < 32; o <<= 1) {
        int u = __shfl_up_sync(0xffffffffu, v, o);
        if (lane >= o) v += u;
    }
    if (lane == 31) sc[wid] = v;
    __syncthreads();
    if (t == 0) {
        int run = 0;
        #pragma unroll
        for (int k = 0; k < 8; k++) { int y = sc[k]; sc[k] = run; run += y; }
        g_bsum[blockIdx.x] = run;
    }
    __syncthreads();
    if (i < N_NODES) g_off[i] = v - c + sc[wid];
}

__global__ void k_scan2() {
    __shared__ int s[512];
    int t = threadIdx.x;
    int v = (t < N_BLK) ? g_bsum[t] : 0;
    s[t] = v;
    __syncthreads();
    #pragma unroll
    for (int o = 1; o < 512; o <<= 1) {
        int x = (t >= o) ? s[t - o] : 0;
        __syncthreads();
        s[t] += x;
        __syncthreads();
    }
    if (t < N_BLK) g_bscan[t] = s[t] - v;
}

__global__ void k_scan3() {
    int t = threadIdx.x;
    int i = blockIdx.x * 256 + t;
    if (i < N_NODES) {
        int o = g_off[i] + g_bscan[blockIdx.x];
        g_off[i] = o;
        g_cur[i] = o;
    }
    if (i == 0) g_off[N_NODES] = N_EDGES;
}

// bucket edges by dst; norm computed inline; 2 edges per thread
__global__ void k_scatter(const float* __restrict__ w) {
    int e0 = blockIdx.x * blockDim.x + threadIdx.x;
    int e1 = e0 + HALF_E;
    int s0 = g_src[e0], d0 = g_dst[e0];
    int s1 = g_src[e1], d1 = g_dst[e1];
    float n0 = g_dinv[s0] * w[e0] * g_dinv[d0];
    float n1 = g_dinv[s1] * w[e1] * g_dinv[d1];
    int p0 = atomicAdd(&g_cur[d0], 1);
    int p1 = atomicAdd(&g_cur[d1], 1);
    g_pk[p0] = make_int2(s0, __float_as_int(n0));
    g_pk[p1] = make_int2(s1, __float_as_int(n1));
}

// ---------------- dense + aggregation -----------------------------------------
__global__ void k_lin1(const float* __restrict__ x, const float* __restrict__ W1) {
    __shared__ float sx[16][65];
    __shared__ float sW[16][65];
    int t = threadIdx.x;                 // 256 threads, 16 nodes/block
    int node0 = blockIdx.x * 16;
    for (int i = t; i < 1024; i += 256) sW[i >> 6][i & 63] = W1[i];
    const float* xb = x + (size_t)node0 * 64;
    for (int i = t; i < 1024; i += 256) sx[i >> 6][i & 63] = xb[i];
    __syncthreads();
    int ni = t >> 4, j = t & 15;
    float acc = 0.0f;
    #pragma unroll
    for (int k = 0; k < 64; k++) acc = fmaf(sx[ni][k], sW[j][k], acc);
    g_h1[(node0 + ni) * 16 + j] = acc;
}

// CSR gather layer 1 (x4 ILP) + fused linear 2
__global__ void k_agg1(const float* __restrict__ b1, const float* __restrict__ W2) {
    __shared__ float sW[16][17];
    __shared__ float sa[16][17];
    int t = threadIdx.x;                 // 256 = 16 nodes x 16 feats
    int ni = t >> 4, f = t & 15;
    sW[ni][f] = W2[t];
    int node = blockIdx.x * 16 + ni;
    int beg = g_off[node], end = g_off[node + 1];
    float a0 = 0.0f, a1 = 0.0f, a2 = 0.0f, a3 = 0.0f;
    int i = beg;
    for (; i + 3 < end; i += 4) {
        int2 p0 = __ldg(&g_pk[i]);
        int2 p1 = __ldg(&g_pk[i + 1]);
        int2 p2 = __ldg(&g_pk[i + 2]);
        int2 p3 = __ldg(&g_pk[i + 3]);
        a0 = fmaf(__int_as_float(p0.y), __ldg(&g_h1[(size_t)p0.x * 16 + f]), a0);
        a1 = fmaf(__int_as_float(p1.y), __ldg(&g_h1[(size_t)p1.x * 16 + f]), a1);
        a2 = fmaf(__int_as_float(p2.y), __ldg(&g_h1[(size_t)p2.x * 16 + f]), a2);
        a3 = fmaf(__int_as_float(p3.y), __ldg(&g_h1[(size_t)p3.x * 16 + f]), a3);
    }
    for (; i < end; i++) {
        int2 p = __ldg(&g_pk[i]);
        a0 = fmaf(__int_as_float(p.y), __ldg(&g_h1[(size_t)p.x * 16 + f]), a0);
    }
    float di = g_dinv[node];
    float acc = di * di * g_h1[node * 16 + f] + ((a0 + a1) + (a2 + a3));
    sa[ni][f] = fmaxf(acc + b1[f], 0.0f);
    __syncthreads();
    float h2 = 0.0f;
    #pragma unroll
    for (int k = 0; k < 16; k++) h2 = fmaf(sa[ni][k], sW[f][k], h2);
    g_h2[node * 16 + f] = h2;
}

// CSR gather layer 2 (x4 ILP) + fused linear 3 + hsum
__global__ void k_agg2(const float* __restrict__ b2, const float* __restrict__ W3) {
    __shared__ float sh[16];
    int t = threadIdx.x;
    int ni = t >> 4, f = t & 15;
    if (t < 16) sh[t] = 0.0f;
    __syncthreads();
    int node = blockIdx.x * 16 + ni;
    int beg = g_off[node], end = g_off[node + 1];
    float a0 = 0.0f, a1 = 0.0f, a2 = 0.0f, a3 = 0.0f;
    int i = beg;
    for (; i + 3 < end; i += 4) {
        int2 p0 = __ldg(&g_pk[i]);
        int2 p1 = __ldg(&g_pk[i + 1]);
        int2 p2 = __ldg(&g_pk[i + 2]);
        int2 p3 = __ldg(&g_pk[i + 3]);
        a0 = fmaf(__int_as_float(p0.y), __ldg(&g_h2[(size_t)p0.x * 16 + f]), a0);
        a1 = fmaf(__int_as_float(p1.y), __ldg(&g_h2[(size_t)p1.x * 16 + f]), a1);
        a2 = fmaf(__int_as_float(p2.y), __ldg(&g_h2[(size_t)p2.x * 16 + f]), a2);
        a3 = fmaf(__int_as_float(p3.y), __ldg(&g_h2[(size_t)p3.x * 16 + f]), a3);
    }
    for (; i < end; i++) {
        int2 p = __ldg(&g_pk[i]);
        a0 = fmaf(__int_as_float(p.y), __ldg(&g_h2[(size_t)p.x * 16 + f]), a0);
    }
    float di = g_dinv[node];
    float acc = di * di * g_h2[node * 16 + f] + ((a0 + a1) + (a2 + a3));
    float hv = fmaxf(acc + b2[f], 0.0f);
    atomicAdd(&sh[f], hv);
    float cv = hv * W3[f];
    #pragma unroll
    for (int o = 8; o; o >>= 1) cv += __shfl_xor_sync(0xffffffffu, cv, o, 16);
    if (f == 0) g_c[node] = cv;
    __syncthreads();
    if (t < 16) atomicAdd(&g_hsum[t], sh[t]);
}

// CSR gather layer 3 (x2 ILP) + logits + fused block max
__global__ void k_agg3(const float* __restrict__ b3, float* __restrict__ out) {
    __shared__ float sm[8];
    int t = threadIdx.x;                 // 256 = 64 nodes x 4 threads
    int ni = t >> 2, q = t & 3;
    int node = blockIdx.x * 64 + ni;
    float mloc = -3.4e38f;
    bool valid = node < N_NODES;
    int beg = 0, end = 0;
    if (valid) { beg = g_off[node]; end = g_off[node + 1]; }
    float a0 = 0.0f, a1 = 0.0f;
    int i = beg + q;
    for (; i + 4 < end; i += 8) {
        int2 p0 = __ldg(&g_pk[i]);
        int2 p1 = __ldg(&g_pk[i + 4]);
        a0 = fmaf(__int_as_float(p0.y), __ldg(&g_c[p0.x]), a0);
        a1 = fmaf(__int_as_float(p1.y), __ldg(&g_c[p1.x]), a1);
    }
    if (i < end) {
        int2 p = __ldg(&g_pk[i]);
        a0 = fmaf(__int_as_float(p.y), __ldg(&g_c[p.x]), a0);
    }
    float acc = a0 + a1;
    #pragma unroll
    for (int o = 2; o; o >>= 1) acc += __shfl_xor_sync(0xffffffffu, acc, o, 4);
    if (valid && q == 0) {
        float di = g_dinv[node];
        float lg = b3[0] + di * di * g_c[node] + acc;
        out[node] = lg;
        mloc = lg;
    }
    mloc = warpMax(mloc);
    if ((t & 31) == 0) sm[t >> 5] = mloc;
    __syncthreads();
    if (t == 0) {
        float m = sm[0];
        #pragma unroll
        for (int k = 1; k < 8; k++) m = fmaxf(m, sm[k]);
        g_pmax[blockIdx.x] = m;
    }
}

// ---------------- softmax + value head ----------------------------------------
__global__ void k_maxfin() {
    __shared__ float sm[16];
    int t = threadIdx.x;                 // 512 threads
    float m = -3.4e38f;
    for (int k = t; k < NTILE64; k += 512) m = fmaxf(m, g_pmax[k]);
    m = warpMax(m);
    if ((t & 31) == 0) sm[t >> 5] = m;
    __syncthreads();
    if (t == 0) {
        float mm = sm[0];
        #pragma unroll
        for (int k = 1; k < 16; k++) mm = fmaxf(mm, sm[k]);
        g_smax = mm;
    }
}

__global__ void k_exp(float* __restrict__ c) {
    __shared__ float sm[8];
    int t = threadIdx.x;
    float mx = g_smax;
    float s = 0.0f;
    for (int i = blockIdx.x * blockDim.x + t; i < N_NODES; i += gridDim.x * blockDim.x) {
        float e = expf(c[i] - mx);
        c[i] = e;
        s += e;
    }
    s = warpSum(s);
    if ((t & 31) == 0) sm[t >> 5] = s;
    __syncthreads();
    if (t < 32) {
        s = (t < 8) ? sm[t] : 0.0f;
        s = warpSum(s);
        if (t == 0) g_part[blockIdx.x] = s;
    }
}

__global__ void k_sumfin(const float* __restrict__ A2w, const float* __restrict__ A2b,
                         float* __restrict__ out) {
    __shared__ float sm[4];
    int t = threadIdx.x;                 // 128 threads
    float s = warpSum(g_part[t]);
    if ((t & 31) == 0) sm[t >> 5] = s;
    __syncthreads();
    if (t == 0) {
        float total = sm[0] + sm[1] + sm[2] + sm[3];
        g_sinv = 1.0f / total;
        float val = A2b[0];
        const float invn = 1.0f / (float)N_NODES;
        #pragma unroll
        for (int k = 0; k < 16; k++) val += g_hsum[k] * invn * A2w[k];
        out[N_NODES] = val;              // value head
    }
}

__global__ void k_scale(float* __restrict__ out) {
    int i = blockIdx.x * blockDim.x + threadIdx.x;
    if (i < N_NODES) out[i] *= g_sinv;
}

// ---------------- launch ------------------------------------------------------
extern "C" void kernel_launch(void* const* d_in, const int* in_sizes, int n_in,
                              void* d_out, int out_size) {
    const float* x   = (const float*)d_in[0];
    const int*   ed  = (const int*)d_in[1];
    const float* w   = (const float*)d_in[2];
    const float* W1  = (const float*)d_in[3];
    const float* b1  = (const float*)d_in[4];
    const float* W2  = (const float*)d_in[5];
    const float* b2  = (const float*)d_in[6];
    const float* W3  = (const float*)d_in[7];
    const float* b3  = (const float*)d_in[8];
    const float* A2w = (const float*)d_in[9];
    const float* A2b = (const float*)d_in[10];
    float* out = (float*)d_out;

    (void)in_sizes; (void)n_in; (void)out_size;

    k_init<<<N_BLK, 256>>>(ed);
    k_deg<<<HALF_E / 256, 256>>>(ed, w);
    k_scan1<<<N_BLK, 256>>>();
    k_scan2<<<1, 512>>>();
    k_scan3<<<N_BLK, 256>>>();
    k_scatter<<<HALF_E / 256, 256>>>(w);

    k_lin1<<<NTILE16, 256>>>(x, W1);
    k_agg1<<<NTILE16, 256>>>(b1, W2);
    k_agg2<<<NTILE16, 256>>>(b2, W3);
    k_agg3<<<NTILE64, 256>>>(b3, out);

    k_maxfin<<<1, 512>>>();
    k_exp<<<128, 256>>>(out);
    k_sumfin<<<1, 128>>>(A2w, A2b, out);
    k_scale<<<N_BLK, 256>>>(out);
}